// round 1
// baseline (speedup 1.0000x reference)
#include <cuda_runtime.h>
#include <math.h>

#define NN 100000
#define EE 1600000
#define BBATCH 64

// ---------------- scratch (static device arrays; no allocation) ----------------
__device__ float    g_xl[NN * 96];      // x @ W_l + b_l
__device__ float    g_xr[NN * 96];      // x @ W_r + b_r
__device__ float    g_logits[EE * 3];   // logits, then reused as exp values
__device__ unsigned g_mx[NN * 3];       // encoded segment max
__device__ float    g_den[NN * 3];      // softmax denominators
__device__ float    g_gat[NN * 96];     // aggregated messages
__device__ float    g_bsum[BBATCH * 32];
__device__ int      g_bcnt[BBATCH];

// order-preserving float -> uint encoding for atomicMax
__device__ __forceinline__ unsigned encf(float f) {
    unsigned u = __float_as_uint(f);
    return (u & 0x80000000u) ? ~u : (u | 0x80000000u);
}
__device__ __forceinline__ float decf(unsigned u) {
    return (u & 0x80000000u) ? __uint_as_float(u & 0x7FFFFFFFu) : __uint_as_float(~u);
}

// ======================= Kernel A: node transforms xl, xr =======================
// xl = x @ W_l + b_l, xr = x @ W_r + b_r     (N x 64) @ (64 x 96)
// 64-node tiles, 128 threads, shared-memory GEMM, thread computes 4 nodes x 12 outs.
__global__ void __launch_bounds__(128) nodeTransformK(
    const float* __restrict__ x,
    const float* __restrict__ Wl, const float* __restrict__ bl,
    const float* __restrict__ Wr, const float* __restrict__ br)
{
    extern __shared__ float sm[];
    float* sWl = sm;               // 64*96
    float* sWr = sWl + 6144;       // 64*96
    float* sX  = sWr + 6144;       // 64*65
    float* sbl = sX + 64 * 65;     // 96
    float* sbr = sbl + 96;         // 96

    int t = threadIdx.x;
    for (int i = t; i < 6144; i += 128) { sWl[i] = Wl[i]; sWr[i] = Wr[i]; }
    for (int i = t; i < 96; i += 128)   { sbl[i] = bl[i]; sbr[i] = br[i]; }

    int n0 = blockIdx.x * 64;
    for (int i = t; i < 4096; i += 128) {
        int r = i >> 6, c = i & 63;
        int n = n0 + r;
        sX[r * 65 + c] = (n < NN) ? x[n * 64 + c] : 0.f;
    }
    __syncthreads();

    int er = t & 15, oc = t >> 4;
    int rb0 = er * 65, rb1 = rb0 + 16 * 65, rb2 = rb1 + 16 * 65, rb3 = rb2 + 16 * 65;

    #pragma unroll
    for (int pass = 0; pass < 2; pass++) {
        const float* W   = pass ? sWr : sWl;
        const float* bia = pass ? sbr : sbl;
        float* dst       = pass ? g_xr : g_xl;

        float acc[4][12];
        #pragma unroll
        for (int i = 0; i < 4; i++)
            #pragma unroll
            for (int j = 0; j < 12; j++) acc[i][j] = 0.f;

        #pragma unroll 4
        for (int k = 0; k < 64; k++) {
            float a0 = sX[rb0 + k], a1 = sX[rb1 + k], a2 = sX[rb2 + k], a3 = sX[rb3 + k];
            const float4* bp = (const float4*)(W + k * 96 + oc * 12);
            float4 q0 = bp[0], q1 = bp[1], q2 = bp[2];
            float bv[12] = {q0.x,q0.y,q0.z,q0.w,q1.x,q1.y,q1.z,q1.w,q2.x,q2.y,q2.z,q2.w};
            #pragma unroll
            for (int j = 0; j < 12; j++) {
                acc[0][j] += a0 * bv[j];
                acc[1][j] += a1 * bv[j];
                acc[2][j] += a2 * bv[j];
                acc[3][j] += a3 * bv[j];
            }
        }
        #pragma unroll
        for (int i = 0; i < 4; i++) {
            int n = n0 + er + 16 * i;
            if (n < NN) {
                float o[12];
                #pragma unroll
                for (int j = 0; j < 12; j++) o[j] = acc[i][j] + bia[oc * 12 + j];
                float4* op = (float4*)(dst + (size_t)n * 96 + oc * 12);
                op[0] = make_float4(o[0], o[1], o[2], o[3]);
                op[1] = make_float4(o[4], o[5], o[6], o[7]);
                op[2] = make_float4(o[8], o[9], o[10], o[11]);
            }
        }
    }
}

// ======================= Kernel B: fused edge kernel =======================
// per 64-edge tile:
//   stage rows = [x[src], edge_attr]          (64 x 96, SMEM)
//   e  = relu(rows @ W_edge + b_edge)         -> global output + SMEM
//   M1 = e @ W_e                               (64 x 96, SMEM)
//   logits[e,h] = sum_c leaky(M1 + xl[src] + xr[dst]) * att ; atomicMax into g_mx
__global__ void __launch_bounds__(128) edgeK(
    const float* __restrict__ x, const float* __restrict__ ea,
    const float* __restrict__ Wedge, const float* __restrict__ bedge,
    const float* __restrict__ We, const float* __restrict__ att,
    const int* __restrict__ srcp, const int* __restrict__ dstp,
    float* __restrict__ e_out)
{
    extern __shared__ float sm[];
    float* sW1  = sm;                 // 96*32
    float* sW2  = sW1 + 3072;         // 32*96
    float* sBuf = sW2 + 3072;         // 64*97
    float* sAtt = sBuf + 64 * 97;     // 96
    float* sBe  = sAtt + 96;          // 32
    int*   sSrc = (int*)(sBe + 32);   // 64
    int*   sDst = sSrc + 64;          // 64

    int t = threadIdx.x;
    for (int i = t; i < 3072; i += 128) { sW1[i] = Wedge[i]; sW2[i] = We[i]; }
    for (int i = t; i < 96; i += 128)   sAtt[i] = att[i];
    if (t < 32) sBe[t] = bedge[t];
    __syncthreads();

    int er = t & 15, oc = t >> 4;
    int rb0 = er * 97, rb1 = rb0 + 16 * 97, rb2 = rb1 + 16 * 97, rb3 = rb2 + 16 * 97;

    for (int tile = blockIdx.x; tile < EE / 64; tile += gridDim.x) {
        int e0 = tile * 64;
        if (t < 64) { sSrc[t] = srcp[e0 + t]; sDst[t] = dstp[e0 + t]; }
        __syncthreads();

        // stage rows
        for (int i = t; i < 64 * 96; i += 128) {
            int r = i / 96, c = i - r * 96;
            float v;
            if (c < 64) v = x[(size_t)sSrc[r] * 64 + c];
            else        v = ea[(size_t)(e0 + r) * 32 + (c - 64)];
            sBuf[r * 97 + c] = v;
        }
        __syncthreads();

        // GEMM1: e = relu(rows @ W_edge + b)
        float acc[4][4];
        #pragma unroll
        for (int i = 0; i < 4; i++)
            #pragma unroll
            for (int j = 0; j < 4; j++) acc[i][j] = 0.f;
        #pragma unroll 4
        for (int k = 0; k < 96; k++) {
            float a0 = sBuf[rb0 + k], a1 = sBuf[rb1 + k], a2 = sBuf[rb2 + k], a3 = sBuf[rb3 + k];
            float4 b = *(const float4*)(sW1 + k * 32 + oc * 4);
            acc[0][0] += a0 * b.x; acc[0][1] += a0 * b.y; acc[0][2] += a0 * b.z; acc[0][3] += a0 * b.w;
            acc[1][0] += a1 * b.x; acc[1][1] += a1 * b.y; acc[1][2] += a1 * b.z; acc[1][3] += a1 * b.w;
            acc[2][0] += a2 * b.x; acc[2][1] += a2 * b.y; acc[2][2] += a2 * b.z; acc[2][3] += a2 * b.w;
            acc[3][0] += a3 * b.x; acc[3][1] += a3 * b.y; acc[3][2] += a3 * b.z; acc[3][3] += a3 * b.w;
        }
        float ev[4][4];
        #pragma unroll
        for (int i = 0; i < 4; i++)
            #pragma unroll
            for (int j = 0; j < 4; j++)
                ev[i][j] = fmaxf(acc[i][j] + sBe[oc * 4 + j], 0.f);
        __syncthreads();  // all GEMM1 reads of sBuf done

        // write e to global + shared (cols 0..31 of sBuf)
        #pragma unroll
        for (int i = 0; i < 4; i++) {
            int row = er + 16 * i;
            *(float4*)(e_out + (size_t)(e0 + row) * 32 + oc * 4) =
                make_float4(ev[i][0], ev[i][1], ev[i][2], ev[i][3]);
            int b = row * 97 + oc * 4;
            sBuf[b + 0] = ev[i][0]; sBuf[b + 1] = ev[i][1];
            sBuf[b + 2] = ev[i][2]; sBuf[b + 3] = ev[i][3];
        }
        __syncthreads();

        // GEMM2: M1 = e @ W_e   (64 x 96)
        float acc2[4][12];
        #pragma unroll
        for (int i = 0; i < 4; i++)
            #pragma unroll
            for (int j = 0; j < 12; j++) acc2[i][j] = 0.f;
        #pragma unroll 8
        for (int k = 0; k < 32; k++) {
            float a0 = sBuf[rb0 + k], a1 = sBuf[rb1 + k], a2 = sBuf[rb2 + k], a3 = sBuf[rb3 + k];
            const float4* bp = (const float4*)(sW2 + k * 96 + oc * 12);
            float4 q0 = bp[0], q1 = bp[1], q2 = bp[2];
            float bv[12] = {q0.x,q0.y,q0.z,q0.w,q1.x,q1.y,q1.z,q1.w,q2.x,q2.y,q2.z,q2.w};
            #pragma unroll
            for (int j = 0; j < 12; j++) {
                acc2[0][j] += a0 * bv[j];
                acc2[1][j] += a1 * bv[j];
                acc2[2][j] += a2 * bv[j];
                acc2[3][j] += a3 * bv[j];
            }
        }
        __syncthreads();  // GEMM2 reads done

        // write M1 into sBuf
        #pragma unroll
        for (int i = 0; i < 4; i++) {
            int rb = (er + 16 * i) * 97 + oc * 12;
            #pragma unroll
            for (int j = 0; j < 12; j++) sBuf[rb + j] = acc2[i][j];
        }
        __syncthreads();

        // logits + atomic max
        for (int p = t; p < 192; p += 128) {
            int eg = p / 3;
            int h  = p - eg * 3;
            int s = sSrc[eg], d = sDst[eg];
            const float4* xlp = (const float4*)(g_xl + (size_t)s * 96 + h * 32);
            const float4* xrp = (const float4*)(g_xr + (size_t)d * 96 + h * 32);
            float accL = 0.f;
            int mb = eg * 97 + h * 32;
            #pragma unroll
            for (int q = 0; q < 8; q++) {
                float4 xa = xlp[q], xb = xrp[q];
                float m0 = sBuf[mb + q * 4 + 0] + xa.x + xb.x;
                float m1 = sBuf[mb + q * 4 + 1] + xa.y + xb.y;
                float m2 = sBuf[mb + q * 4 + 2] + xa.z + xb.z;
                float m3 = sBuf[mb + q * 4 + 3] + xa.w + xb.w;
                m0 = (m0 > 0.f) ? m0 : 0.2f * m0;
                m1 = (m1 > 0.f) ? m1 : 0.2f * m1;
                m2 = (m2 > 0.f) ? m2 : 0.2f * m2;
                m3 = (m3 > 0.f) ? m3 : 0.2f * m3;
                accL += m0 * sAtt[h * 32 + q * 4 + 0];
                accL += m1 * sAtt[h * 32 + q * 4 + 1];
                accL += m2 * sAtt[h * 32 + q * 4 + 2];
                accL += m3 * sAtt[h * 32 + q * 4 + 3];
            }
            g_logits[(size_t)(e0 + eg) * 3 + h] = accL;
            atomicMax(&g_mx[d * 3 + h], encf(accL));
        }
        __syncthreads();  // protect sSrc/sBuf before next tile
    }
}

// ======================= Kernel C: exp + denominator =======================
__global__ void __launch_bounds__(256) pass2K(const int* __restrict__ dstp)
{
    int p = blockIdx.x * 256 + threadIdx.x;
    if (p >= EE * 3) return;
    int e = p / 3;
    int h = p - e * 3;
    int d = dstp[e];
    float lg = g_logits[p];
    float mx = decf(g_mx[d * 3 + h]);
    float ex = expf(lg - mx);
    g_logits[p] = ex;
    atomicAdd(&g_den[d * 3 + h], ex);
}

// ======================= Kernel D: message scatter =======================
// one warp per edge; lane handles channels {l, l+32, l+64} (head = chunk index)
__global__ void __launch_bounds__(256) scatterK(const int* __restrict__ srcp,
                                                const int* __restrict__ dstp)
{
    int e = blockIdx.x * 8 + (threadIdx.x >> 5);
    int lane = threadIdx.x & 31;
    int s = srcp[e], d = dstp[e];
    float a0 = g_logits[(size_t)e * 3 + 0] / g_den[d * 3 + 0];
    float a1 = g_logits[(size_t)e * 3 + 1] / g_den[d * 3 + 1];
    float a2 = g_logits[(size_t)e * 3 + 2] / g_den[d * 3 + 2];
    const float* xl = g_xl + (size_t)s * 96;
    float* go = g_gat + (size_t)d * 96;
    atomicAdd(&go[lane],      a0 * xl[lane]);
    atomicAdd(&go[lane + 32], a1 * xl[lane + 32]);
    atomicAdd(&go[lane + 64], a2 * xl[lane + 64]);
}

// ======================= Kernel E: node_mlp_2 + batch sums =======================
// x_new = relu([gat + bias_gat, glob[batch]] @ W_n2 + b_n2)   (N x 128) @ (128 x 32)
__global__ void __launch_bounds__(128) node2K(
    const float* __restrict__ glob, const int* __restrict__ batch,
    const float* __restrict__ Wn2, const float* __restrict__ bn2,
    const float* __restrict__ bias_gat, float* __restrict__ xnew)
{
    extern __shared__ float sm[];
    float* sW  = sm;               // 128*32
    float* sR  = sW + 4096;        // 64*129
    float* sBg = sR + 64 * 129;    // 96
    float* sBn = sBg + 96;         // 32
    int* sBat  = (int*)(sBn + 32); // 64

    int t = threadIdx.x;
    for (int i = t; i < 4096; i += 128) sW[i] = Wn2[i];
    for (int i = t; i < 96; i += 128)   sBg[i] = bias_gat[i];
    if (t < 32) sBn[t] = bn2[t];

    int n0 = blockIdx.x * 64;
    if (t < 64) {
        int n = n0 + t;
        int bb = 0;
        if (n < NN) {
            bb = batch[n];
            atomicAdd(&g_bcnt[bb], 1);
        }
        sBat[t] = bb;
    }
    __syncthreads();

    for (int i = t; i < 64 * 128; i += 128) {
        int r = i >> 7, c = i & 127;
        int n = n0 + r;
        float v = 0.f;
        if (n < NN) {
            if (c < 96) v = g_gat[(size_t)n * 96 + c] + sBg[c];
            else        v = glob[sBat[r] * 32 + (c - 96)];
        }
        sR[r * 129 + c] = v;
    }
    __syncthreads();

    int er = t & 15, oc = t >> 4;
    int rb0 = er * 129, rb1 = rb0 + 16 * 129, rb2 = rb1 + 16 * 129, rb3 = rb2 + 16 * 129;

    float acc[4][4];
    #pragma unroll
    for (int i = 0; i < 4; i++)
        #pragma unroll
        for (int j = 0; j < 4; j++) acc[i][j] = 0.f;
    #pragma unroll 4
    for (int k = 0; k < 128; k++) {
        float a0 = sR[rb0 + k], a1 = sR[rb1 + k], a2 = sR[rb2 + k], a3 = sR[rb3 + k];
        float4 b = *(const float4*)(sW + k * 32 + oc * 4);
        acc[0][0] += a0 * b.x; acc[0][1] += a0 * b.y; acc[0][2] += a0 * b.z; acc[0][3] += a0 * b.w;
        acc[1][0] += a1 * b.x; acc[1][1] += a1 * b.y; acc[1][2] += a1 * b.z; acc[1][3] += a1 * b.w;
        acc[2][0] += a2 * b.x; acc[2][1] += a2 * b.y; acc[2][2] += a2 * b.z; acc[2][3] += a2 * b.w;
        acc[3][0] += a3 * b.x; acc[3][1] += a3 * b.y; acc[3][2] += a3 * b.z; acc[3][3] += a3 * b.w;
    }

    #pragma unroll
    for (int i = 0; i < 4; i++) {
        int n = n0 + er + 16 * i;
        if (n < NN) {
            int bb = sBat[er + 16 * i];
            float v0 = fmaxf(acc[i][0] + sBn[oc * 4 + 0], 0.f);
            float v1 = fmaxf(acc[i][1] + sBn[oc * 4 + 1], 0.f);
            float v2 = fmaxf(acc[i][2] + sBn[oc * 4 + 2], 0.f);
            float v3 = fmaxf(acc[i][3] + sBn[oc * 4 + 3], 0.f);
            *(float4*)(xnew + (size_t)n * 32 + oc * 4) = make_float4(v0, v1, v2, v3);
            atomicAdd(&g_bsum[bb * 32 + oc * 4 + 0], v0);
            atomicAdd(&g_bsum[bb * 32 + oc * 4 + 1], v1);
            atomicAdd(&g_bsum[bb * 32 + oc * 4 + 2], v2);
            atomicAdd(&g_bsum[bb * 32 + oc * 4 + 3], v3);
        }
    }
}

// ======================= Kernel F: global MLP =======================
__global__ void __launch_bounds__(256) globalK(
    const float* __restrict__ glob, const float* __restrict__ Wg,
    const float* __restrict__ bg, float* __restrict__ u_out)
{
    int p = blockIdx.x * 256 + threadIdx.x;
    if (p >= BBATCH * 32) return;
    int b = p >> 5, c = p & 31;
    float acc = bg[c];
    #pragma unroll
    for (int k = 0; k < 32; k++) acc += glob[b * 32 + k] * Wg[k * 32 + c];
    float cnt = fmaxf((float)g_bcnt[b], 1.f);
    float inv = 1.f / cnt;
    #pragma unroll
    for (int k = 0; k < 32; k++) acc += (g_bsum[b * 32 + k] * inv) * Wg[(32 + k) * 32 + c];
    u_out[p] = fmaxf(acc, 0.f);
}

// ======================= launch =======================
extern "C" void kernel_launch(void* const* d_in, const int* in_sizes, int n_in,
                              void* d_out, int out_size)
{
    const float* x        = (const float*)d_in[0];
    const float* ea       = (const float*)d_in[1];
    const float* glob     = (const float*)d_in[2];
    const float* W_edge   = (const float*)d_in[3];
    const float* b_edge   = (const float*)d_in[4];
    const float* W_l      = (const float*)d_in[5];
    const float* b_l      = (const float*)d_in[6];
    const float* W_r      = (const float*)d_in[7];
    const float* b_r      = (const float*)d_in[8];
    const float* W_e      = (const float*)d_in[9];
    const float* att      = (const float*)d_in[10];
    const float* bias_gat = (const float*)d_in[11];
    const float* W_n2     = (const float*)d_in[12];
    const float* b_n2     = (const float*)d_in[13];
    const float* W_g      = (const float*)d_in[14];
    const float* b_g      = (const float*)d_in[15];
    const int* eidx       = (const int*)d_in[16];
    const int* batch      = (const int*)d_in[17];
    const int* srcp = eidx;
    const int* dstp = eidx + EE;

    float* out  = (float*)d_out;
    float* o_x  = out;                       // [N,32]
    float* o_e  = out + (size_t)NN * 32;     // [E,32]
    float* o_u  = o_e + (size_t)EE * 32;     // [B,32]

    const int SMEM_A = (6144 * 2 + 64 * 65 + 192) * 4;          // 66560
    const int SMEM_B = (3072 + 3072 + 64 * 97 + 96 + 32) * 4 + 128 * 4;  // 50432
    const int SMEM_E = (4096 + 64 * 129 + 96 + 32) * 4 + 64 * 4;         // 50176

    cudaFuncSetAttribute(nodeTransformK, cudaFuncAttributeMaxDynamicSharedMemorySize, SMEM_A);
    cudaFuncSetAttribute(edgeK,          cudaFuncAttributeMaxDynamicSharedMemorySize, SMEM_B);
    cudaFuncSetAttribute(node2K,         cudaFuncAttributeMaxDynamicSharedMemorySize, SMEM_E);

    void* p;
    cudaGetSymbolAddress(&p, g_mx);   cudaMemsetAsync(p, 0, (size_t)NN * 3 * 4);
    cudaGetSymbolAddress(&p, g_den);  cudaMemsetAsync(p, 0, (size_t)NN * 3 * 4);
    cudaGetSymbolAddress(&p, g_gat);  cudaMemsetAsync(p, 0, (size_t)NN * 96 * 4);
    cudaGetSymbolAddress(&p, g_bsum); cudaMemsetAsync(p, 0, (size_t)BBATCH * 32 * 4);
    cudaGetSymbolAddress(&p, g_bcnt); cudaMemsetAsync(p, 0, (size_t)BBATCH * 4);

    nodeTransformK<<<(NN + 63) / 64, 128, SMEM_A>>>(x, W_l, b_l, W_r, b_r);
    edgeK<<<592, 128, SMEM_B>>>(x, ea, W_edge, b_edge, W_e, att, srcp, dstp, o_e);
    pass2K<<<(EE * 3 + 255) / 256, 256>>>(dstp);
    scatterK<<<EE / 8, 256>>>(srcp, dstp);
    node2K<<<(NN + 63) / 64, 128, SMEM_E>>>(glob, batch, W_n2, b_n2, bias_gat, o_x);
    globalK<<<(BBATCH * 32 + 255) / 256, 256>>>(glob, W_g, b_g, o_u);
}

// round 2
// speedup vs baseline: 1.5381x; 1.5381x over previous
#include <cuda_runtime.h>
#include <math.h>

#define NN 100000
#define EE 1600000
#define BBATCH 64

// ---------------- scratch (static device arrays; no allocation) ----------------
__device__ float    g_xl[NN * 96];      // x @ W_l + b_l
__device__ float    g_xr[NN * 96];      // x @ W_r + b_r
__device__ float    g_P [NN * 32];      // x @ W_edge[:64] + b_edge
__device__ float    g_logits[EE * 3];   // logits, then reused as exp values
__device__ unsigned g_mx[NN * 3];       // encoded segment max
__device__ float    g_den[NN * 3];      // softmax denominators
__device__ float    g_gat[NN * 96];     // aggregated messages
__device__ float    g_bsum[BBATCH * 32];
__device__ int      g_bcnt[BBATCH];

// order-preserving float -> uint encoding for atomicMax (all finite values encode > 0)
__device__ __forceinline__ unsigned encf(float f) {
    unsigned u = __float_as_uint(f);
    return (u & 0x80000000u) ? ~u : (u | 0x80000000u);
}
__device__ __forceinline__ float decf(unsigned u) {
    return (u & 0x80000000u) ? __uint_as_float(u & 0x7FFFFFFFu) : __uint_as_float(~u);
}

// ======================= Kernel A: node transforms xl, xr, P =======================
// xl = x@W_l+b_l, xr = x@W_r+b_r  (Nx64 @ 64x96);  P = x@W_edge[:64]+b_edge (Nx64 @ 64x32)
__global__ void __launch_bounds__(128) nodeTransformK(
    const float* __restrict__ x,
    const float* __restrict__ Wl, const float* __restrict__ bl,
    const float* __restrict__ Wr, const float* __restrict__ br,
    const float* __restrict__ Wedge, const float* __restrict__ bedge)
{
    extern __shared__ float sm[];
    float* sWl = sm;               // 64*96
    float* sWr = sWl + 6144;       // 64*96
    float* sWp = sWr + 6144;       // 64*32
    float* sX  = sWp + 2048;       // 64*65
    float* sbl = sX + 64 * 65;     // 96
    float* sbr = sbl + 96;         // 96
    float* sbp = sbr + 96;         // 32

    int t = threadIdx.x;
    for (int i = t; i < 6144; i += 128) { sWl[i] = Wl[i]; sWr[i] = Wr[i]; }
    for (int i = t; i < 2048; i += 128) sWp[i] = Wedge[i];
    for (int i = t; i < 96; i += 128)   { sbl[i] = bl[i]; sbr[i] = br[i]; }
    if (t < 32) sbp[t] = bedge[t];

    int n0 = blockIdx.x * 64;
    for (int i = t; i < 4096; i += 128) {
        int r = i >> 6, c = i & 63;
        int n = n0 + r;
        sX[r * 65 + c] = (n < NN) ? x[(size_t)n * 64 + c] : 0.f;
    }
    __syncthreads();

    int er = t & 15, oc = t >> 4;
    int rb0 = er * 65, rb1 = rb0 + 16 * 65, rb2 = rb1 + 16 * 65, rb3 = rb2 + 16 * 65;

    #pragma unroll
    for (int pass = 0; pass < 2; pass++) {
        const float* W   = pass ? sWr : sWl;
        const float* bia = pass ? sbr : sbl;
        float* dst       = pass ? g_xr : g_xl;

        float acc[4][12];
        #pragma unroll
        for (int i = 0; i < 4; i++)
            #pragma unroll
            for (int j = 0; j < 12; j++) acc[i][j] = 0.f;

        #pragma unroll 4
        for (int k = 0; k < 64; k++) {
            float a0 = sX[rb0 + k], a1 = sX[rb1 + k], a2 = sX[rb2 + k], a3 = sX[rb3 + k];
            const float4* bp = (const float4*)(W + k * 96 + oc * 12);
            float4 q0 = bp[0], q1 = bp[1], q2 = bp[2];
            float bv[12] = {q0.x,q0.y,q0.z,q0.w,q1.x,q1.y,q1.z,q1.w,q2.x,q2.y,q2.z,q2.w};
            #pragma unroll
            for (int j = 0; j < 12; j++) {
                acc[0][j] += a0 * bv[j];
                acc[1][j] += a1 * bv[j];
                acc[2][j] += a2 * bv[j];
                acc[3][j] += a3 * bv[j];
            }
        }
        #pragma unroll
        for (int i = 0; i < 4; i++) {
            int n = n0 + er + 16 * i;
            if (n < NN) {
                float o[12];
                #pragma unroll
                for (int j = 0; j < 12; j++) o[j] = acc[i][j] + bia[oc * 12 + j];
                float4* op = (float4*)(dst + (size_t)n * 96 + oc * 12);
                op[0] = make_float4(o[0], o[1], o[2], o[3]);
                op[1] = make_float4(o[4], o[5], o[6], o[7]);
                op[2] = make_float4(o[8], o[9], o[10], o[11]);
            }
        }
    }

    // P pass: 8 col groups of 4
    {
        float acc[4][4];
        #pragma unroll
        for (int i = 0; i < 4; i++)
            #pragma unroll
            for (int j = 0; j < 4; j++) acc[i][j] = 0.f;
        #pragma unroll 8
        for (int k = 0; k < 64; k++) {
            float a0 = sX[rb0 + k], a1 = sX[rb1 + k], a2 = sX[rb2 + k], a3 = sX[rb3 + k];
            float4 b = *(const float4*)(sWp + k * 32 + oc * 4);
            acc[0][0] += a0 * b.x; acc[0][1] += a0 * b.y; acc[0][2] += a0 * b.z; acc[0][3] += a0 * b.w;
            acc[1][0] += a1 * b.x; acc[1][1] += a1 * b.y; acc[1][2] += a1 * b.z; acc[1][3] += a1 * b.w;
            acc[2][0] += a2 * b.x; acc[2][1] += a2 * b.y; acc[2][2] += a2 * b.z; acc[2][3] += a2 * b.w;
            acc[3][0] += a3 * b.x; acc[3][1] += a3 * b.y; acc[3][2] += a3 * b.z; acc[3][3] += a3 * b.w;
        }
        #pragma unroll
        for (int i = 0; i < 4; i++) {
            int n = n0 + er + 16 * i;
            if (n < NN) {
                *(float4*)(g_P + (size_t)n * 32 + oc * 4) = make_float4(
                    acc[i][0] + sbp[oc * 4 + 0], acc[i][1] + sbp[oc * 4 + 1],
                    acc[i][2] + sbp[oc * 4 + 2], acc[i][3] + sbp[oc * 4 + 3]);
            }
        }
    }
}

// ======================= Kernel B: fused edge kernel =======================
// per 64-edge tile:
//   e  = relu(P[src] + edge_attr @ W_edge[64:])   -> global + SMEM
//   M1 = e @ W_e (registers), logits = sum leaky(M1+xl[src]+xr[dst])*att
//   logits -> global; atomicMax segment max
__global__ void __launch_bounds__(128) edgeK(
    const float* __restrict__ ea,
    const float* __restrict__ Wedge,
    const float* __restrict__ We, const float* __restrict__ att,
    const int* __restrict__ srcp, const int* __restrict__ dstp,
    float* __restrict__ e_out)
{
    extern __shared__ float sm[];
    float* sWb  = sm;                 // 32*32  (W_edge rows 64..95)
    float* sW2  = sWb + 1024;         // 32*96  (W_e)
    float* sEA  = sW2 + 3072;         // 64*33
    float* sE   = sEA + 64 * 33;      // 64*33
    float* sLog = sE + 64 * 33;       // 64*3
    int*   sSrc = (int*)(sLog + 192); // 64
    int*   sDst = sSrc + 64;          // 64

    int t = threadIdx.x;
    for (int i = t; i < 1024; i += 128) sWb[i] = Wedge[2048 + i];
    for (int i = t; i < 3072; i += 128) sW2[i] = We[i];

    int er = t & 15, oc = t >> 4;
    int c0 = oc * 12;

    float attv[12];
    #pragma unroll
    for (int j = 0; j < 12; j++) attv[j] = att[c0 + j];

    // head split for this thread's 12 columns
    int hA = c0 >> 5;
    int hB = (c0 + 11) >> 5;
    int split = (hB > hA) ? (hB * 32 - c0) : 12;

    int rb0 = er * 33, rb1 = rb0 + 16 * 33, rb2 = rb1 + 16 * 33, rb3 = rb2 + 16 * 33;

    __syncthreads();

    for (int tile = blockIdx.x; tile < EE / 64; tile += gridDim.x) {
        int e0 = tile * 64;
        if (t < 64) { sSrc[t] = srcp[e0 + t]; sDst[t] = dstp[e0 + t]; }
        for (int i = t; i < 192; i += 128) sLog[i] = 0.f;
        // stage edge_attr (64x32) into padded smem
        for (int i = t; i < 512; i += 128) {
            int r = i >> 3, c4 = i & 7;
            float4 v = *(const float4*)(ea + (size_t)(e0 + r) * 32 + c4 * 4);
            int b = r * 33 + c4 * 4;
            sEA[b] = v.x; sEA[b + 1] = v.y; sEA[b + 2] = v.z; sEA[b + 3] = v.w;
        }
        __syncthreads();

        // GEMM-T: tmp = ea @ Wb  (64x32), then e = relu(tmp + P[src])
        {
            float acc[4][4];
            #pragma unroll
            for (int i = 0; i < 4; i++)
                #pragma unroll
                for (int j = 0; j < 4; j++) acc[i][j] = 0.f;
            #pragma unroll 8
            for (int k = 0; k < 32; k++) {
                float a0 = sEA[rb0 + k], a1 = sEA[rb1 + k], a2 = sEA[rb2 + k], a3 = sEA[rb3 + k];
                float4 b = *(const float4*)(sWb + k * 32 + oc * 4);
                acc[0][0] += a0 * b.x; acc[0][1] += a0 * b.y; acc[0][2] += a0 * b.z; acc[0][3] += a0 * b.w;
                acc[1][0] += a1 * b.x; acc[1][1] += a1 * b.y; acc[1][2] += a1 * b.z; acc[1][3] += a1 * b.w;
                acc[2][0] += a2 * b.x; acc[2][1] += a2 * b.y; acc[2][2] += a2 * b.z; acc[2][3] += a2 * b.w;
                acc[3][0] += a3 * b.x; acc[3][1] += a3 * b.y; acc[3][2] += a3 * b.z; acc[3][3] += a3 * b.w;
            }
            int oc4 = oc * 4;
            #pragma unroll
            for (int i = 0; i < 4; i++) {
                int row = er + 16 * i;
                int s = sSrc[row];
                float4 p = *(const float4*)(g_P + (size_t)s * 32 + oc4);
                float v0 = fmaxf(acc[i][0] + p.x, 0.f);
                float v1 = fmaxf(acc[i][1] + p.y, 0.f);
                float v2 = fmaxf(acc[i][2] + p.z, 0.f);
                float v3 = fmaxf(acc[i][3] + p.w, 0.f);
                *(float4*)(e_out + (size_t)(e0 + row) * 32 + oc4) = make_float4(v0, v1, v2, v3);
                int b = row * 33 + oc4;
                sE[b] = v0; sE[b + 1] = v1; sE[b + 2] = v2; sE[b + 3] = v3;
            }
        }
        __syncthreads();

        // GEMM2 (registers): M1 = e @ W_e (64x96), fused logits
        {
            float acc2[4][12];
            #pragma unroll
            for (int i = 0; i < 4; i++)
                #pragma unroll
                for (int j = 0; j < 12; j++) acc2[i][j] = 0.f;
            #pragma unroll 8
            for (int k = 0; k < 32; k++) {
                float a0 = sE[rb0 + k], a1 = sE[rb1 + k], a2 = sE[rb2 + k], a3 = sE[rb3 + k];
                const float4* bp = (const float4*)(sW2 + k * 96 + c0);
                float4 q0 = bp[0], q1 = bp[1], q2 = bp[2];
                float bv[12] = {q0.x,q0.y,q0.z,q0.w,q1.x,q1.y,q1.z,q1.w,q2.x,q2.y,q2.z,q2.w};
                #pragma unroll
                for (int j = 0; j < 12; j++) {
                    acc2[0][j] += a0 * bv[j];
                    acc2[1][j] += a1 * bv[j];
                    acc2[2][j] += a2 * bv[j];
                    acc2[3][j] += a3 * bv[j];
                }
            }
            #pragma unroll
            for (int i = 0; i < 4; i++) {
                int row = er + 16 * i;
                int s = sSrc[row], d = sDst[row];
                const float4* xlp = (const float4*)(g_xl + (size_t)s * 96 + c0);
                const float4* xrp = (const float4*)(g_xr + (size_t)d * 96 + c0);
                float pA = 0.f, pB = 0.f;
                #pragma unroll
                for (int q = 0; q < 3; q++) {
                    float4 xa = xlp[q], xb = xrp[q];
                    float mm[4];
                    mm[0] = acc2[i][q * 4 + 0] + xa.x + xb.x;
                    mm[1] = acc2[i][q * 4 + 1] + xa.y + xb.y;
                    mm[2] = acc2[i][q * 4 + 2] + xa.z + xb.z;
                    mm[3] = acc2[i][q * 4 + 3] + xa.w + xb.w;
                    #pragma unroll
                    for (int jj = 0; jj < 4; jj++) {
                        int j = q * 4 + jj;
                        float m = mm[jj];
                        m = (m > 0.f) ? m : 0.2f * m;
                        float v = m * attv[j];
                        if (j < split) pA += v; else pB += v;
                    }
                }
                atomicAdd(&sLog[row * 3 + hA], pA);
                if (hB > hA) atomicAdd(&sLog[row * 3 + hB], pB);
            }
        }
        __syncthreads();

        for (int i = t; i < 192; i += 128) {
            int eg = i / 3, h = i - eg * 3;
            float v = sLog[i];
            g_logits[(size_t)(e0 + eg) * 3 + h] = v;
            atomicMax(&g_mx[sDst[eg] * 3 + h], encf(v));
        }
        __syncthreads();
    }
}

// ======================= Kernel C: exp + denominator =======================
__global__ void __launch_bounds__(256) pass2K(const int* __restrict__ dstp)
{
    int e = blockIdx.x * 256 + threadIdx.x;
    if (e >= EE) return;
    int d = dstp[e];
    #pragma unroll
    for (int h = 0; h < 3; h++) {
        float lg = g_logits[(size_t)e * 3 + h];
        float mx = decf(g_mx[d * 3 + h]);
        float ex = expf(lg - mx);
        g_logits[(size_t)e * 3 + h] = ex;
        atomicAdd(&g_den[d * 3 + h], ex);
    }
}

// ======================= Kernel D: message scatter (red.v4) =======================
// one warp per edge; lanes 0..23 each handle 4 channels via red.global.add.v4.f32
__global__ void __launch_bounds__(256) scatterK(const int* __restrict__ srcp,
                                                const int* __restrict__ dstp)
{
    int e = blockIdx.x * 8 + (threadIdx.x >> 5);
    int lane = threadIdx.x & 31;
    int s = srcp[e], d = dstp[e];
    float a_own = 0.f;
    if ((lane & 7) == 0 && lane < 24) {
        int h = lane >> 3;
        a_own = g_logits[(size_t)e * 3 + h] / g_den[d * 3 + h];
    }
    float alpha = __shfl_sync(0xffffffffu, a_own, lane & 24);
    if (lane < 24) {
        float4 xv = *(const float4*)(g_xl + (size_t)s * 96 + lane * 4);
        float* gp = g_gat + (size_t)d * 96 + lane * 4;
        asm volatile("red.global.add.v4.f32 [%0], {%1,%2,%3,%4};"
                     :: "l"(gp), "f"(alpha * xv.x), "f"(alpha * xv.y),
                        "f"(alpha * xv.z), "f"(alpha * xv.w)
                     : "memory");
    }
}

// ======================= Kernel E: node_mlp_2 + batch sums =======================
__global__ void __launch_bounds__(128) node2K(
    const float* __restrict__ glob, const int* __restrict__ batch,
    const float* __restrict__ Wn2, const float* __restrict__ bn2,
    const float* __restrict__ bias_gat, float* __restrict__ xnew)
{
    extern __shared__ float sm[];
    float* sW  = sm;               // 128*32
    float* sR  = sW + 4096;        // 64*129
    float* sBg = sR + 64 * 129;    // 96
    float* sBn = sBg + 96;         // 32
    int* sBat  = (int*)(sBn + 32); // 64

    int t = threadIdx.x;
    for (int i = t; i < 4096; i += 128) sW[i] = Wn2[i];
    for (int i = t; i < 96; i += 128)   sBg[i] = bias_gat[i];
    if (t < 32) sBn[t] = bn2[t];

    int n0 = blockIdx.x * 64;
    if (t < 64) {
        int n = n0 + t;
        int bb = 0;
        if (n < NN) {
            bb = batch[n];
            atomicAdd(&g_bcnt[bb], 1);
        }
        sBat[t] = bb;
    }
    __syncthreads();

    for (int i = t; i < 64 * 128; i += 128) {
        int r = i >> 7, c = i & 127;
        int n = n0 + r;
        float v = 0.f;
        if (n < NN) {
            if (c < 96) v = g_gat[(size_t)n * 96 + c] + sBg[c];
            else        v = glob[sBat[r] * 32 + (c - 96)];
        }
        sR[r * 129 + c] = v;
    }
    __syncthreads();

    int er = t & 15, oc = t >> 4;
    int rb0 = er * 129, rb1 = rb0 + 16 * 129, rb2 = rb1 + 16 * 129, rb3 = rb2 + 16 * 129;

    float acc[4][4];
    #pragma unroll
    for (int i = 0; i < 4; i++)
        #pragma unroll
        for (int j = 0; j < 4; j++) acc[i][j] = 0.f;
    #pragma unroll 4
    for (int k = 0; k < 128; k++) {
        float a0 = sR[rb0 + k], a1 = sR[rb1 + k], a2 = sR[rb2 + k], a3 = sR[rb3 + k];
        float4 b = *(const float4*)(sW + k * 32 + oc * 4);
        acc[0][0] += a0 * b.x; acc[0][1] += a0 * b.y; acc[0][2] += a0 * b.z; acc[0][3] += a0 * b.w;
        acc[1][0] += a1 * b.x; acc[1][1] += a1 * b.y; acc[1][2] += a1 * b.z; acc[1][3] += a1 * b.w;
        acc[2][0] += a2 * b.x; acc[2][1] += a2 * b.y; acc[2][2] += a2 * b.z; acc[2][3] += a2 * b.w;
        acc[3][0] += a3 * b.x; acc[3][1] += a3 * b.y; acc[3][2] += a3 * b.z; acc[3][3] += a3 * b.w;
    }

    #pragma unroll
    for (int i = 0; i < 4; i++) {
        int n = n0 + er + 16 * i;
        if (n < NN) {
            int bb = sBat[er + 16 * i];
            float v0 = fmaxf(acc[i][0] + sBn[oc * 4 + 0], 0.f);
            float v1 = fmaxf(acc[i][1] + sBn[oc * 4 + 1], 0.f);
            float v2 = fmaxf(acc[i][2] + sBn[oc * 4 + 2], 0.f);
            float v3 = fmaxf(acc[i][3] + sBn[oc * 4 + 3], 0.f);
            *(float4*)(xnew + (size_t)n * 32 + oc * 4) = make_float4(v0, v1, v2, v3);
            atomicAdd(&g_bsum[bb * 32 + oc * 4 + 0], v0);
            atomicAdd(&g_bsum[bb * 32 + oc * 4 + 1], v1);
            atomicAdd(&g_bsum[bb * 32 + oc * 4 + 2], v2);
            atomicAdd(&g_bsum[bb * 32 + oc * 4 + 3], v3);
        }
    }
}

// ======================= Kernel F: global MLP =======================
__global__ void __launch_bounds__(256) globalK(
    const float* __restrict__ glob, const float* __restrict__ Wg,
    const float* __restrict__ bg, float* __restrict__ u_out)
{
    int p = blockIdx.x * 256 + threadIdx.x;
    if (p >= BBATCH * 32) return;
    int b = p >> 5, c = p & 31;
    float acc = bg[c];
    #pragma unroll
    for (int k = 0; k < 32; k++) acc += glob[b * 32 + k] * Wg[k * 32 + c];
    float cnt = fmaxf((float)g_bcnt[b], 1.f);
    float inv = 1.f / cnt;
    #pragma unroll
    for (int k = 0; k < 32; k++) acc += (g_bsum[b * 32 + k] * inv) * Wg[(32 + k) * 32 + c];
    u_out[p] = fmaxf(acc, 0.f);
}

// ======================= launch =======================
extern "C" void kernel_launch(void* const* d_in, const int* in_sizes, int n_in,
                              void* d_out, int out_size)
{
    const float* x        = (const float*)d_in[0];
    const float* ea       = (const float*)d_in[1];
    const float* glob     = (const float*)d_in[2];
    const float* W_edge   = (const float*)d_in[3];
    const float* b_edge   = (const float*)d_in[4];
    const float* W_l      = (const float*)d_in[5];
    const float* b_l      = (const float*)d_in[6];
    const float* W_r      = (const float*)d_in[7];
    const float* b_r      = (const float*)d_in[8];
    const float* W_e      = (const float*)d_in[9];
    const float* att      = (const float*)d_in[10];
    const float* bias_gat = (const float*)d_in[11];
    const float* W_n2     = (const float*)d_in[12];
    const float* b_n2     = (const float*)d_in[13];
    const float* W_g      = (const float*)d_in[14];
    const float* b_g      = (const float*)d_in[15];
    const int* eidx       = (const int*)d_in[16];
    const int* batch      = (const int*)d_in[17];
    const int* srcp = eidx;
    const int* dstp = eidx + EE;

    float* out  = (float*)d_out;
    float* o_x  = out;                       // [N,32]
    float* o_e  = out + (size_t)NN * 32;     // [E,32]
    float* o_u  = o_e + (size_t)EE * 32;     // [B,32]

    const int SMEM_A = (6144 + 6144 + 2048 + 64 * 65 + 96 + 96 + 32) * 4;   // 74880
    const int SMEM_B = (1024 + 3072 + 64 * 33 + 64 * 33 + 192) * 4 + 128 * 4; // 34560
    const int SMEM_E = (4096 + 64 * 129 + 96 + 32) * 4 + 64 * 4;              // 50176

    cudaFuncSetAttribute(nodeTransformK, cudaFuncAttributeMaxDynamicSharedMemorySize, SMEM_A);
    cudaFuncSetAttribute(edgeK,          cudaFuncAttributeMaxDynamicSharedMemorySize, SMEM_B);
    cudaFuncSetAttribute(node2K,         cudaFuncAttributeMaxDynamicSharedMemorySize, SMEM_E);

    void* p;
    cudaGetSymbolAddress(&p, g_mx);   cudaMemsetAsync(p, 0, (size_t)NN * 3 * 4);
    cudaGetSymbolAddress(&p, g_den);  cudaMemsetAsync(p, 0, (size_t)NN * 3 * 4);
    cudaGetSymbolAddress(&p, g_gat);  cudaMemsetAsync(p, 0, (size_t)NN * 96 * 4);
    cudaGetSymbolAddress(&p, g_bsum); cudaMemsetAsync(p, 0, (size_t)BBATCH * 32 * 4);
    cudaGetSymbolAddress(&p, g_bcnt); cudaMemsetAsync(p, 0, (size_t)BBATCH * 4);

    nodeTransformK<<<(NN + 63) / 64, 128, SMEM_A>>>(x, W_l, b_l, W_r, b_r, W_edge, b_edge);
    edgeK<<<592, 128, SMEM_B>>>(ea, W_edge, W_e, att, srcp, dstp, o_e);
    pass2K<<<(EE + 255) / 256, 256>>>(dstp);
    scatterK<<<EE / 8, 256>>>(srcp, dstp);
    node2K<<<(NN + 63) / 64, 128, SMEM_E>>>(glob, batch, W_n2, b_n2, bias_gat, o_x);
    globalK<<<(BBATCH * 32 + 255) / 256, 256>>>(glob, W_g, b_g, o_u);
}

// round 3
// speedup vs baseline: 1.6150x; 1.0500x over previous
#include <cuda_runtime.h>
#include <math.h>

#define NN 100000
#define EE 1600000
#define BBATCH 64

typedef unsigned long long u64t;

// ---------------- scratch (static device arrays; no allocation) ----------------
__device__ float    g_xl[NN * 96];      // x @ W_l + b_l
__device__ float    g_xr[NN * 96];      // x @ W_r + b_r
__device__ float    g_P [NN * 32];      // x @ W_edge[:64] + b_edge
__device__ float    g_logits[EE * 3];   // logits, then reused as exp values
__device__ unsigned g_mx[NN * 3];       // encoded segment max
__device__ float    g_den[NN * 3];      // softmax denominators
__device__ float    g_gat[NN * 96];     // aggregated messages
__device__ float    g_bsum[BBATCH * 32];
__device__ int      g_bcnt[BBATCH];

// order-preserving float -> uint encoding for atomicMax
__device__ __forceinline__ unsigned encf(float f) {
    unsigned u = __float_as_uint(f);
    return (u & 0x80000000u) ? ~u : (u | 0x80000000u);
}
__device__ __forceinline__ float decf(unsigned u) {
    return (u & 0x80000000u) ? __uint_as_float(u & 0x7FFFFFFFu) : __uint_as_float(~u);
}

// ---------------- packed f32x2 helpers ----------------
__device__ __forceinline__ void fma2(u64t& d, u64t a, u64t b) {
    asm("fma.rn.f32x2 %0, %1, %2, %0;" : "+l"(d) : "l"(a), "l"(b));
}
__device__ __forceinline__ u64t pk(float a) {
    u64t r;
    asm("mov.b64 %0, {%1, %1};" : "=l"(r) : "f"(a));
    return r;
}
__device__ __forceinline__ void upk(u64t v, float& lo, float& hi) {
    asm("mov.b64 {%0, %1}, %2;" : "=f"(lo), "=f"(hi) : "l"(v));
}

// ======================= Kernel A: node transforms xl, xr, P =======================
__global__ void __launch_bounds__(128) nodeTransformK(
    const float* __restrict__ x,
    const float* __restrict__ Wl, const float* __restrict__ bl,
    const float* __restrict__ Wr, const float* __restrict__ br,
    const float* __restrict__ Wedge, const float* __restrict__ bedge)
{
    extern __shared__ float sm[];
    float* sWl = sm;               // 64*96
    float* sWr = sWl + 6144;       // 64*96
    float* sWp = sWr + 6144;       // 64*32
    float* sX  = sWp + 2048;       // 64*66 (pad 2 keeps 8B alignment)
    float* sbl = sX + 64 * 66;     // 96
    float* sbr = sbl + 96;         // 96
    float* sbp = sbr + 96;         // 32

    int t = threadIdx.x;
    for (int i = t; i < 6144; i += 128) { sWl[i] = Wl[i]; sWr[i] = Wr[i]; }
    for (int i = t; i < 2048; i += 128) sWp[i] = Wedge[i];
    for (int i = t; i < 96; i += 128)   { sbl[i] = bl[i]; sbr[i] = br[i]; }
    if (t < 32) sbp[t] = bedge[t];

    int n0 = blockIdx.x * 64;
    for (int i = t; i < 4096; i += 128) {
        int r = i >> 6, c = i & 63;
        int n = n0 + r;
        sX[r * 66 + c] = (n < NN) ? x[(size_t)n * 64 + c] : 0.f;
    }
    __syncthreads();

    int er = t & 15, oc = t >> 4;
    int rb0 = er * 66, rb1 = rb0 + 16 * 66, rb2 = rb1 + 16 * 66, rb3 = rb2 + 16 * 66;

    #pragma unroll
    for (int pass = 0; pass < 2; pass++) {
        const float* W   = pass ? sWr : sWl;
        const float* bia = pass ? sbr : sbl;
        float* dst       = pass ? g_xr : g_xl;

        u64t acc[4][6];
        #pragma unroll
        for (int i = 0; i < 4; i++)
            #pragma unroll
            for (int j = 0; j < 6; j++) acc[i][j] = 0ull;

        #pragma unroll 4
        for (int k = 0; k < 64; k++) {
            u64t a0 = pk(sX[rb0 + k]), a1 = pk(sX[rb1 + k]);
            u64t a2 = pk(sX[rb2 + k]), a3 = pk(sX[rb3 + k]);
            const u64t* bp = (const u64t*)(W + k * 96 + oc * 12);
            u64t b0 = bp[0], b1 = bp[1], b2 = bp[2], b3 = bp[3], b4 = bp[4], b5 = bp[5];
            fma2(acc[0][0], a0, b0); fma2(acc[0][1], a0, b1); fma2(acc[0][2], a0, b2);
            fma2(acc[0][3], a0, b3); fma2(acc[0][4], a0, b4); fma2(acc[0][5], a0, b5);
            fma2(acc[1][0], a1, b0); fma2(acc[1][1], a1, b1); fma2(acc[1][2], a1, b2);
            fma2(acc[1][3], a1, b3); fma2(acc[1][4], a1, b4); fma2(acc[1][5], a1, b5);
            fma2(acc[2][0], a2, b0); fma2(acc[2][1], a2, b1); fma2(acc[2][2], a2, b2);
            fma2(acc[2][3], a2, b3); fma2(acc[2][4], a2, b4); fma2(acc[2][5], a2, b5);
            fma2(acc[3][0], a3, b0); fma2(acc[3][1], a3, b1); fma2(acc[3][2], a3, b2);
            fma2(acc[3][3], a3, b3); fma2(acc[3][4], a3, b4); fma2(acc[3][5], a3, b5);
        }
        #pragma unroll
        for (int i = 0; i < 4; i++) {
            int n = n0 + er + 16 * i;
            if (n < NN) {
                float o[12];
                #pragma unroll
                for (int j = 0; j < 6; j++) upk(acc[i][j], o[2 * j], o[2 * j + 1]);
                #pragma unroll
                for (int j = 0; j < 12; j++) o[j] += bia[oc * 12 + j];
                float4* op = (float4*)(dst + (size_t)n * 96 + oc * 12);
                op[0] = make_float4(o[0], o[1], o[2], o[3]);
                op[1] = make_float4(o[4], o[5], o[6], o[7]);
                op[2] = make_float4(o[8], o[9], o[10], o[11]);
            }
        }
    }

    // P pass
    {
        u64t acc[4][2];
        #pragma unroll
        for (int i = 0; i < 4; i++) { acc[i][0] = 0ull; acc[i][1] = 0ull; }
        #pragma unroll 8
        for (int k = 0; k < 64; k++) {
            u64t a0 = pk(sX[rb0 + k]), a1 = pk(sX[rb1 + k]);
            u64t a2 = pk(sX[rb2 + k]), a3 = pk(sX[rb3 + k]);
            const u64t* bp = (const u64t*)(sWp + k * 32 + oc * 4);
            u64t b0 = bp[0], b1 = bp[1];
            fma2(acc[0][0], a0, b0); fma2(acc[0][1], a0, b1);
            fma2(acc[1][0], a1, b0); fma2(acc[1][1], a1, b1);
            fma2(acc[2][0], a2, b0); fma2(acc[2][1], a2, b1);
            fma2(acc[3][0], a3, b0); fma2(acc[3][1], a3, b1);
        }
        #pragma unroll
        for (int i = 0; i < 4; i++) {
            int n = n0 + er + 16 * i;
            if (n < NN) {
                float o0, o1, o2, o3;
                upk(acc[i][0], o0, o1);
                upk(acc[i][1], o2, o3);
                *(float4*)(g_P + (size_t)n * 32 + oc * 4) = make_float4(
                    o0 + sbp[oc * 4 + 0], o1 + sbp[oc * 4 + 1],
                    o2 + sbp[oc * 4 + 2], o3 + sbp[oc * 4 + 3]);
            }
        }
    }
}

// ======================= Kernel B: fused edge kernel =======================
__global__ void __launch_bounds__(128) edgeK(
    const float* __restrict__ ea,
    const float* __restrict__ Wedge,
    const float* __restrict__ We, const float* __restrict__ att,
    const int* __restrict__ srcp, const int* __restrict__ dstp,
    float* __restrict__ e_out)
{
    extern __shared__ float sm[];
    float* sWb  = sm;                 // 32*32  (W_edge rows 64..95)
    float* sW2  = sWb + 1024;         // 32*96  (W_e)
    float* sEA  = sW2 + 3072;         // 64*34 (pad 2)
    float* sE   = sEA + 64 * 34;      // 64*34
    float* sLog = sE + 64 * 34;       // 64*3
    int*   sSrc = (int*)(sLog + 192); // 64
    int*   sDst = sSrc + 64;          // 64

    int t = threadIdx.x;
    for (int i = t; i < 1024; i += 128) sWb[i] = Wedge[2048 + i];
    for (int i = t; i < 3072; i += 128) sW2[i] = We[i];

    int er = t & 15, oc = t >> 4;
    int c0 = oc * 12;

    float attv[12];
    #pragma unroll
    for (int j = 0; j < 12; j++) attv[j] = att[c0 + j];

    int hA = c0 >> 5;
    int hB = (c0 + 11) >> 5;
    int split = (hB > hA) ? (hB * 32 - c0) : 12;

    int rb0 = er * 34, rb1 = rb0 + 16 * 34, rb2 = rb1 + 16 * 34, rb3 = rb2 + 16 * 34;

    __syncthreads();

    for (int tile = blockIdx.x; tile < EE / 64; tile += gridDim.x) {
        int e0 = tile * 64;
        if (t < 64) { sSrc[t] = srcp[e0 + t]; sDst[t] = dstp[e0 + t]; }
        for (int i = t; i < 192; i += 128) sLog[i] = 0.f;
        for (int i = t; i < 512; i += 128) {
            int r = i >> 3, c4 = i & 7;
            float4 v = *(const float4*)(ea + (size_t)(e0 + r) * 32 + c4 * 4);
            int b = r * 34 + c4 * 4;
            sEA[b] = v.x; sEA[b + 1] = v.y; sEA[b + 2] = v.z; sEA[b + 3] = v.w;
        }
        __syncthreads();

        // GEMM1: tmp = ea @ Wb, e = relu(tmp + P[src])
        {
            u64t acc[4][2];
            #pragma unroll
            for (int i = 0; i < 4; i++) { acc[i][0] = 0ull; acc[i][1] = 0ull; }
            #pragma unroll 8
            for (int k = 0; k < 32; k++) {
                u64t a0 = pk(sEA[rb0 + k]), a1 = pk(sEA[rb1 + k]);
                u64t a2 = pk(sEA[rb2 + k]), a3 = pk(sEA[rb3 + k]);
                const u64t* bp = (const u64t*)(sWb + k * 32 + oc * 4);
                u64t b0 = bp[0], b1 = bp[1];
                fma2(acc[0][0], a0, b0); fma2(acc[0][1], a0, b1);
                fma2(acc[1][0], a1, b0); fma2(acc[1][1], a1, b1);
                fma2(acc[2][0], a2, b0); fma2(acc[2][1], a2, b1);
                fma2(acc[3][0], a3, b0); fma2(acc[3][1], a3, b1);
            }
            int oc4 = oc * 4;
            #pragma unroll
            for (int i = 0; i < 4; i++) {
                int row = er + 16 * i;
                int s = sSrc[row];
                float4 p = *(const float4*)(g_P + (size_t)s * 32 + oc4);
                float o0, o1, o2, o3;
                upk(acc[i][0], o0, o1);
                upk(acc[i][1], o2, o3);
                float v0 = fmaxf(o0 + p.x, 0.f);
                float v1 = fmaxf(o1 + p.y, 0.f);
                float v2 = fmaxf(o2 + p.z, 0.f);
                float v3 = fmaxf(o3 + p.w, 0.f);
                *(float4*)(e_out + (size_t)(e0 + row) * 32 + oc4) = make_float4(v0, v1, v2, v3);
                int b = row * 34 + oc4;
                sE[b] = v0; sE[b + 1] = v1; sE[b + 2] = v2; sE[b + 3] = v3;
            }
        }
        __syncthreads();

        // GEMM2: M1 = e @ W_e (registers), fused logits
        {
            u64t acc2[4][6];
            #pragma unroll
            for (int i = 0; i < 4; i++)
                #pragma unroll
                for (int j = 0; j < 6; j++) acc2[i][j] = 0ull;
            #pragma unroll 8
            for (int k = 0; k < 32; k++) {
                u64t a0 = pk(sE[rb0 + k]), a1 = pk(sE[rb1 + k]);
                u64t a2 = pk(sE[rb2 + k]), a3 = pk(sE[rb3 + k]);
                const u64t* bp = (const u64t*)(sW2 + k * 96 + c0);
                u64t b0 = bp[0], b1 = bp[1], b2 = bp[2], b3 = bp[3], b4 = bp[4], b5 = bp[5];
                fma2(acc2[0][0], a0, b0); fma2(acc2[0][1], a0, b1); fma2(acc2[0][2], a0, b2);
                fma2(acc2[0][3], a0, b3); fma2(acc2[0][4], a0, b4); fma2(acc2[0][5], a0, b5);
                fma2(acc2[1][0], a1, b0); fma2(acc2[1][1], a1, b1); fma2(acc2[1][2], a1, b2);
                fma2(acc2[1][3], a1, b3); fma2(acc2[1][4], a1, b4); fma2(acc2[1][5], a1, b5);
                fma2(acc2[2][0], a2, b0); fma2(acc2[2][1], a2, b1); fma2(acc2[2][2], a2, b2);
                fma2(acc2[2][3], a2, b3); fma2(acc2[2][4], a2, b4); fma2(acc2[2][5], a2, b5);
                fma2(acc2[3][0], a3, b0); fma2(acc2[3][1], a3, b1); fma2(acc2[3][2], a3, b2);
                fma2(acc2[3][3], a3, b3); fma2(acc2[3][4], a3, b4); fma2(acc2[3][5], a3, b5);
            }
            #pragma unroll
            for (int i = 0; i < 4; i++) {
                int row = er + 16 * i;
                int s = sSrc[row], d = sDst[row];
                const float4* xlp = (const float4*)(g_xl + (size_t)s * 96 + c0);
                const float4* xrp = (const float4*)(g_xr + (size_t)d * 96 + c0);
                float m1v[12];
                #pragma unroll
                for (int j = 0; j < 6; j++) upk(acc2[i][j], m1v[2 * j], m1v[2 * j + 1]);
                float pA = 0.f, pB = 0.f;
                #pragma unroll
                for (int q = 0; q < 3; q++) {
                    float4 xa = xlp[q], xb = xrp[q];
                    float mm[4];
                    mm[0] = m1v[q * 4 + 0] + xa.x + xb.x;
                    mm[1] = m1v[q * 4 + 1] + xa.y + xb.y;
                    mm[2] = m1v[q * 4 + 2] + xa.z + xb.z;
                    mm[3] = m1v[q * 4 + 3] + xa.w + xb.w;
                    #pragma unroll
                    for (int jj = 0; jj < 4; jj++) {
                        int j = q * 4 + jj;
                        float m = mm[jj];
                        m = (m > 0.f) ? m : 0.2f * m;
                        float v = m * attv[j];
                        if (j < split) pA += v; else pB += v;
                    }
                }
                atomicAdd(&sLog[row * 3 + hA], pA);
                if (hB > hA) atomicAdd(&sLog[row * 3 + hB], pB);
            }
        }
        __syncthreads();

        for (int i = t; i < 192; i += 128) {
            int eg = i / 3, h = i - eg * 3;
            float v = sLog[i];
            g_logits[(size_t)(e0 + eg) * 3 + h] = v;
            atomicMax(&g_mx[sDst[eg] * 3 + h], encf(v));
        }
        __syncthreads();
    }
}

// ======================= Kernel C: exp + denominator =======================
__global__ void __launch_bounds__(256) pass2K(const int* __restrict__ dstp)
{
    int e = blockIdx.x * 256 + threadIdx.x;
    if (e >= EE) return;
    int d = dstp[e];
    #pragma unroll
    for (int h = 0; h < 3; h++) {
        float lg = g_logits[(size_t)e * 3 + h];
        float mx = decf(g_mx[d * 3 + h]);
        float ex = __expf(lg - mx);
        g_logits[(size_t)e * 3 + h] = ex;
        atomicAdd(&g_den[d * 3 + h], ex);
    }
}

// ======================= Kernel D: message scatter (red.v4) =======================
__global__ void __launch_bounds__(256) scatterK(const int* __restrict__ srcp,
                                                const int* __restrict__ dstp)
{
    int e = blockIdx.x * 8 + (threadIdx.x >> 5);
    int lane = threadIdx.x & 31;
    int s = srcp[e], d = dstp[e];
    float a_own = 0.f;
    if ((lane & 7) == 0 && lane < 24) {
        int h = lane >> 3;
        a_own = g_logits[(size_t)e * 3 + h] / g_den[d * 3 + h];
    }
    float alpha = __shfl_sync(0xffffffffu, a_own, lane & 24);
    if (lane < 24) {
        float4 xv = *(const float4*)(g_xl + (size_t)s * 96 + lane * 4);
        float* gp = g_gat + (size_t)d * 96 + lane * 4;
        asm volatile("red.global.add.v4.f32 [%0], {%1,%2,%3,%4};"
                     :: "l"(gp), "f"(alpha * xv.x), "f"(alpha * xv.y),
                        "f"(alpha * xv.z), "f"(alpha * xv.w)
                     : "memory");
    }
}

// ======================= Kernel E: node_mlp_2 + batch sums =======================
__global__ void __launch_bounds__(128) node2K(
    const float* __restrict__ glob, const int* __restrict__ batch,
    const float* __restrict__ Wn2, const float* __restrict__ bn2,
    const float* __restrict__ bias_gat, float* __restrict__ xnew)
{
    extern __shared__ float sm[];
    float* sW  = sm;               // 128*32
    float* sR  = sW + 4096;        // 64*130 (pad 2)
    float* sBg = sR + 64 * 130;    // 96
    float* sBn = sBg + 96;         // 32
    int* sBat  = (int*)(sBn + 32); // 64

    int t = threadIdx.x;
    for (int i = t; i < 4096; i += 128) sW[i] = Wn2[i];
    for (int i = t; i < 96; i += 128)   sBg[i] = bias_gat[i];
    if (t < 32) sBn[t] = bn2[t];

    int n0 = blockIdx.x * 64;
    if (t < 64) {
        int n = n0 + t;
        int bb = 0;
        if (n < NN) {
            bb = batch[n];
            atomicAdd(&g_bcnt[bb], 1);
        }
        sBat[t] = bb;
    }
    __syncthreads();

    for (int i = t; i < 64 * 128; i += 128) {
        int r = i >> 7, c = i & 127;
        int n = n0 + r;
        float v = 0.f;
        if (n < NN) {
            if (c < 96) v = g_gat[(size_t)n * 96 + c] + sBg[c];
            else        v = glob[sBat[r] * 32 + (c - 96)];
        }
        sR[r * 130 + c] = v;
    }
    __syncthreads();

    int er = t & 15, oc = t >> 4;
    int rb0 = er * 130, rb1 = rb0 + 16 * 130, rb2 = rb1 + 16 * 130, rb3 = rb2 + 16 * 130;

    u64t acc[4][2];
    #pragma unroll
    for (int i = 0; i < 4; i++) { acc[i][0] = 0ull; acc[i][1] = 0ull; }
    #pragma unroll 4
    for (int k = 0; k < 128; k++) {
        u64t a0 = pk(sR[rb0 + k]), a1 = pk(sR[rb1 + k]);
        u64t a2 = pk(sR[rb2 + k]), a3 = pk(sR[rb3 + k]);
        const u64t* bp = (const u64t*)(sW + k * 32 + oc * 4);
        u64t b0 = bp[0], b1 = bp[1];
        fma2(acc[0][0], a0, b0); fma2(acc[0][1], a0, b1);
        fma2(acc[1][0], a1, b0); fma2(acc[1][1], a1, b1);
        fma2(acc[2][0], a2, b0); fma2(acc[2][1], a2, b1);
        fma2(acc[3][0], a3, b0); fma2(acc[3][1], a3, b1);
    }

    #pragma unroll
    for (int i = 0; i < 4; i++) {
        int n = n0 + er + 16 * i;
        if (n < NN) {
            int bb = sBat[er + 16 * i];
            float o0, o1, o2, o3;
            upk(acc[i][0], o0, o1);
            upk(acc[i][1], o2, o3);
            float v0 = fmaxf(o0 + sBn[oc * 4 + 0], 0.f);
            float v1 = fmaxf(o1 + sBn[oc * 4 + 1], 0.f);
            float v2 = fmaxf(o2 + sBn[oc * 4 + 2], 0.f);
            float v3 = fmaxf(o3 + sBn[oc * 4 + 3], 0.f);
            *(float4*)(xnew + (size_t)n * 32 + oc * 4) = make_float4(v0, v1, v2, v3);
            atomicAdd(&g_bsum[bb * 32 + oc * 4 + 0], v0);
            atomicAdd(&g_bsum[bb * 32 + oc * 4 + 1], v1);
            atomicAdd(&g_bsum[bb * 32 + oc * 4 + 2], v2);
            atomicAdd(&g_bsum[bb * 32 + oc * 4 + 3], v3);
        }
    }
}

// ======================= Kernel F: global MLP =======================
__global__ void __launch_bounds__(256) globalK(
    const float* __restrict__ glob, const float* __restrict__ Wg,
    const float* __restrict__ bg, float* __restrict__ u_out)
{
    int p = blockIdx.x * 256 + threadIdx.x;
    if (p >= BBATCH * 32) return;
    int b = p >> 5, c = p & 31;
    float acc = bg[c];
    #pragma unroll
    for (int k = 0; k < 32; k++) acc += glob[b * 32 + k] * Wg[k * 32 + c];
    float cnt = fmaxf((float)g_bcnt[b], 1.f);
    float inv = 1.f / cnt;
    #pragma unroll
    for (int k = 0; k < 32; k++) acc += (g_bsum[b * 32 + k] * inv) * Wg[(32 + k) * 32 + c];
    u_out[p] = fmaxf(acc, 0.f);
}

// ======================= launch =======================
extern "C" void kernel_launch(void* const* d_in, const int* in_sizes, int n_in,
                              void* d_out, int out_size)
{
    const float* x        = (const float*)d_in[0];
    const float* ea       = (const float*)d_in[1];
    const float* glob     = (const float*)d_in[2];
    const float* W_edge   = (const float*)d_in[3];
    const float* b_edge   = (const float*)d_in[4];
    const float* W_l      = (const float*)d_in[5];
    const float* b_l      = (const float*)d_in[6];
    const float* W_r      = (const float*)d_in[7];
    const float* b_r      = (const float*)d_in[8];
    const float* W_e      = (const float*)d_in[9];
    const float* att      = (const float*)d_in[10];
    const float* bias_gat = (const float*)d_in[11];
    const float* W_n2     = (const float*)d_in[12];
    const float* b_n2     = (const float*)d_in[13];
    const float* W_g      = (const float*)d_in[14];
    const float* b_g      = (const float*)d_in[15];
    const int* eidx       = (const int*)d_in[16];
    const int* batch      = (const int*)d_in[17];
    const int* srcp = eidx;
    const int* dstp = eidx + EE;

    float* out  = (float*)d_out;
    float* o_x  = out;                       // [N,32]
    float* o_e  = out + (size_t)NN * 32;     // [E,32]
    float* o_u  = o_e + (size_t)EE * 32;     // [B,32]

    const int SMEM_A = (6144 + 6144 + 2048 + 64 * 66 + 96 + 96 + 32) * 4;     // ~75136
    const int SMEM_B = (1024 + 3072 + 64 * 34 + 64 * 34 + 192) * 4 + 128 * 4; // ~35072
    const int SMEM_E = (4096 + 64 * 130 + 96 + 32) * 4 + 64 * 4;              // ~50432

    cudaFuncSetAttribute(nodeTransformK, cudaFuncAttributeMaxDynamicSharedMemorySize, SMEM_A);
    cudaFuncSetAttribute(edgeK,          cudaFuncAttributeMaxDynamicSharedMemorySize, SMEM_B);
    cudaFuncSetAttribute(node2K,         cudaFuncAttributeMaxDynamicSharedMemorySize, SMEM_E);

    void* p;
    cudaGetSymbolAddress(&p, g_mx);   cudaMemsetAsync(p, 0, (size_t)NN * 3 * 4);
    cudaGetSymbolAddress(&p, g_den);  cudaMemsetAsync(p, 0, (size_t)NN * 3 * 4);
    cudaGetSymbolAddress(&p, g_gat);  cudaMemsetAsync(p, 0, (size_t)NN * 96 * 4);
    cudaGetSymbolAddress(&p, g_bsum); cudaMemsetAsync(p, 0, (size_t)BBATCH * 32 * 4);
    cudaGetSymbolAddress(&p, g_bcnt); cudaMemsetAsync(p, 0, (size_t)BBATCH * 4);

    nodeTransformK<<<(NN + 63) / 64, 128, SMEM_A>>>(x, W_l, b_l, W_r, b_r, W_edge, b_edge);
    edgeK<<<592, 128, SMEM_B>>>(ea, W_edge, W_e, att, srcp, dstp, o_e);
    pass2K<<<(EE + 255) / 256, 256>>>(dstp);
    scatterK<<<EE / 8, 256>>>(srcp, dstp);
    node2K<<<(NN + 63) / 64, 128, SMEM_E>>>(glob, batch, W_n2, b_n2, bias_gat, o_x);
    globalK<<<(BBATCH * 32 + 255) / 256, 256>>>(glob, W_g, b_g, o_u);
}

// round 4
// speedup vs baseline: 1.7266x; 1.0691x over previous
#include <cuda_runtime.h>
#include <math.h>

#define NN 100000
#define EE 1600000
#define BBATCH 64

typedef unsigned long long u64t;

// ---------------- scratch (static device arrays; no allocation) ----------------
__device__ float    g_xl[NN * 96];      // x @ W_l + b_l
__device__ float    g_xr[NN * 96];      // x @ W_r + b_r
__device__ float    g_P [NN * 32];      // x @ W_edge[:64] + b_edge
__device__ float    g_logits[EE * 3];   // logits -> exp -> alpha (staged reuse)
__device__ unsigned g_mx[NN * 3];       // encoded segment max
__device__ float    g_den[NN * 3];      // softmax denominators
__device__ float    g_gat[NN * 96];     // aggregated messages
__device__ float    g_bsum[BBATCH * 32];
__device__ int      g_bcnt[BBATCH];

// order-preserving float -> uint encoding for atomicMax
__device__ __forceinline__ unsigned encf(float f) {
    unsigned u = __float_as_uint(f);
    return (u & 0x80000000u) ? ~u : (u | 0x80000000u);
}
__device__ __forceinline__ float decf(unsigned u) {
    return (u & 0x80000000u) ? __uint_as_float(u & 0x7FFFFFFFu) : __uint_as_float(~u);
}

// ---------------- packed f32x2 helpers ----------------
__device__ __forceinline__ void fma2(u64t& d, u64t a, u64t b) {
    asm("fma.rn.f32x2 %0, %1, %2, %0;" : "+l"(d) : "l"(a), "l"(b));
}
__device__ __forceinline__ u64t pk(float a) {
    u64t r;
    asm("mov.b64 %0, {%1, %1};" : "=l"(r) : "f"(a));
    return r;
}
__device__ __forceinline__ void upk(u64t v, float& lo, float& hi) {
    asm("mov.b64 {%0, %1}, %2;" : "=f"(lo), "=f"(hi) : "l"(v));
}

// ======================= Kernel A: node transforms xl, xr, P =======================
__global__ void __launch_bounds__(128) nodeTransformK(
    const float* __restrict__ x,
    const float* __restrict__ Wl, const float* __restrict__ bl,
    const float* __restrict__ Wr, const float* __restrict__ br,
    const float* __restrict__ Wedge, const float* __restrict__ bedge)
{
    extern __shared__ float sm[];
    float* sWl = sm;               // 64*96
    float* sWr = sWl + 6144;       // 64*96
    float* sWp = sWr + 6144;       // 64*32
    float* sX  = sWp + 2048;       // 64*66
    float* sbl = sX + 64 * 66;     // 96
    float* sbr = sbl + 96;         // 96
    float* sbp = sbr + 96;         // 32

    int t = threadIdx.x;
    for (int i = t; i < 6144; i += 128) { sWl[i] = Wl[i]; sWr[i] = Wr[i]; }
    for (int i = t; i < 2048; i += 128) sWp[i] = Wedge[i];
    for (int i = t; i < 96; i += 128)   { sbl[i] = bl[i]; sbr[i] = br[i]; }
    if (t < 32) sbp[t] = bedge[t];

    int n0 = blockIdx.x * 64;
    for (int i = t; i < 4096; i += 128) {
        int r = i >> 6, c = i & 63;
        int n = n0 + r;
        sX[r * 66 + c] = (n < NN) ? x[(size_t)n * 64 + c] : 0.f;
    }
    __syncthreads();

    int er = t & 15, oc = t >> 4;
    int rb0 = er * 66, rb1 = rb0 + 16 * 66, rb2 = rb1 + 16 * 66, rb3 = rb2 + 16 * 66;

    #pragma unroll
    for (int pass = 0; pass < 2; pass++) {
        const float* W   = pass ? sWr : sWl;
        const float* bia = pass ? sbr : sbl;
        float* dst       = pass ? g_xr : g_xl;

        u64t acc[4][6];
        #pragma unroll
        for (int i = 0; i < 4; i++)
            #pragma unroll
            for (int j = 0; j < 6; j++) acc[i][j] = 0ull;

        #pragma unroll 4
        for (int k = 0; k < 64; k++) {
            u64t a0 = pk(sX[rb0 + k]), a1 = pk(sX[rb1 + k]);
            u64t a2 = pk(sX[rb2 + k]), a3 = pk(sX[rb3 + k]);
            const u64t* bp = (const u64t*)(W + k * 96 + oc * 12);
            u64t b0 = bp[0], b1 = bp[1], b2 = bp[2], b3 = bp[3], b4 = bp[4], b5 = bp[5];
            fma2(acc[0][0], a0, b0); fma2(acc[0][1], a0, b1); fma2(acc[0][2], a0, b2);
            fma2(acc[0][3], a0, b3); fma2(acc[0][4], a0, b4); fma2(acc[0][5], a0, b5);
            fma2(acc[1][0], a1, b0); fma2(acc[1][1], a1, b1); fma2(acc[1][2], a1, b2);
            fma2(acc[1][3], a1, b3); fma2(acc[1][4], a1, b4); fma2(acc[1][5], a1, b5);
            fma2(acc[2][0], a2, b0); fma2(acc[2][1], a2, b1); fma2(acc[2][2], a2, b2);
            fma2(acc[2][3], a2, b3); fma2(acc[2][4], a2, b4); fma2(acc[2][5], a2, b5);
            fma2(acc[3][0], a3, b0); fma2(acc[3][1], a3, b1); fma2(acc[3][2], a3, b2);
            fma2(acc[3][3], a3, b3); fma2(acc[3][4], a3, b4); fma2(acc[3][5], a3, b5);
        }
        #pragma unroll
        for (int i = 0; i < 4; i++) {
            int n = n0 + er + 16 * i;
            if (n < NN) {
                float o[12];
                #pragma unroll
                for (int j = 0; j < 6; j++) upk(acc[i][j], o[2 * j], o[2 * j + 1]);
                #pragma unroll
                for (int j = 0; j < 12; j++) o[j] += bia[oc * 12 + j];
                float4* op = (float4*)(dst + (size_t)n * 96 + oc * 12);
                op[0] = make_float4(o[0], o[1], o[2], o[3]);
                op[1] = make_float4(o[4], o[5], o[6], o[7]);
                op[2] = make_float4(o[8], o[9], o[10], o[11]);
            }
        }
    }

    // P pass
    {
        u64t acc[4][2];
        #pragma unroll
        for (int i = 0; i < 4; i++) { acc[i][0] = 0ull; acc[i][1] = 0ull; }
        #pragma unroll 8
        for (int k = 0; k < 64; k++) {
            u64t a0 = pk(sX[rb0 + k]), a1 = pk(sX[rb1 + k]);
            u64t a2 = pk(sX[rb2 + k]), a3 = pk(sX[rb3 + k]);
            const u64t* bp = (const u64t*)(sWp + k * 32 + oc * 4);
            u64t b0 = bp[0], b1 = bp[1];
            fma2(acc[0][0], a0, b0); fma2(acc[0][1], a0, b1);
            fma2(acc[1][0], a1, b0); fma2(acc[1][1], a1, b1);
            fma2(acc[2][0], a2, b0); fma2(acc[2][1], a2, b1);
            fma2(acc[3][0], a3, b0); fma2(acc[3][1], a3, b1);
        }
        #pragma unroll
        for (int i = 0; i < 4; i++) {
            int n = n0 + er + 16 * i;
            if (n < NN) {
                float o0, o1, o2, o3;
                upk(acc[i][0], o0, o1);
                upk(acc[i][1], o2, o3);
                *(float4*)(g_P + (size_t)n * 32 + oc * 4) = make_float4(
                    o0 + sbp[oc * 4 + 0], o1 + sbp[oc * 4 + 1],
                    o2 + sbp[oc * 4 + 2], o3 + sbp[oc * 4 + 3]);
            }
        }
    }
}

// ======================= Kernel B: fused edge kernel =======================
// thread map: oc = t&7 (column group of 12), er = t>>3 (row 0..15); rows er+16i.
// 8 column-group threads of a row are contiguous lanes -> logits reduced by shuffles.
__global__ void __launch_bounds__(128) edgeK(
    const float* __restrict__ ea,
    const float* __restrict__ Wedge,
    const float* __restrict__ We, const float* __restrict__ att,
    const int* __restrict__ srcp, const int* __restrict__ dstp,
    float* __restrict__ e_out)
{
    extern __shared__ float sm[];
    float* sWb  = sm;                 // 32*32  (W_edge rows 64..95)
    float* sW2  = sWb + 1024;         // 32*96  (W_e)
    float* sEA  = sW2 + 3072;         // 64*34
    float* sE   = sEA + 64 * 34;      // 64*34
    int*   sSrc = (int*)(sE + 64 * 34); // 64
    int*   sDst = sSrc + 64;          // 64

    int t = threadIdx.x;
    for (int i = t; i < 1024; i += 128) sWb[i] = Wedge[2048 + i];
    for (int i = t; i < 3072; i += 128) sW2[i] = We[i];

    int oc = t & 7, er = t >> 3;
    int c0 = oc * 12;

    float attv[12];
    #pragma unroll
    for (int j = 0; j < 12; j++) attv[j] = att[c0 + j];

    int hA = c0 >> 5;
    int hB = (c0 + 11) >> 5;
    int split = (hB > hA) ? (hB * 32 - c0) : 12;

    int rb0 = er * 34, rb1 = rb0 + 16 * 34, rb2 = rb1 + 16 * 34, rb3 = rb2 + 16 * 34;

    __syncthreads();

    for (int tile = blockIdx.x; tile < EE / 64; tile += gridDim.x) {
        int e0 = tile * 64;
        if (t < 64) { sSrc[t] = srcp[e0 + t]; sDst[t] = dstp[e0 + t]; }
        for (int i = t; i < 512; i += 128) {
            int r = i >> 3, c4 = i & 7;
            float4 v = *(const float4*)(ea + (size_t)(e0 + r) * 32 + c4 * 4);
            int b = r * 34 + c4 * 4;
            sEA[b] = v.x; sEA[b + 1] = v.y; sEA[b + 2] = v.z; sEA[b + 3] = v.w;
        }
        __syncthreads();

        // GEMM1: tmp = ea @ Wb, e = relu(tmp + P[src])
        {
            u64t acc[4][2];
            #pragma unroll
            for (int i = 0; i < 4; i++) { acc[i][0] = 0ull; acc[i][1] = 0ull; }
            #pragma unroll 8
            for (int k = 0; k < 32; k++) {
                u64t a0 = pk(sEA[rb0 + k]), a1 = pk(sEA[rb1 + k]);
                u64t a2 = pk(sEA[rb2 + k]), a3 = pk(sEA[rb3 + k]);
                const u64t* bp = (const u64t*)(sWb + k * 32 + oc * 4);
                u64t b0 = bp[0], b1 = bp[1];
                fma2(acc[0][0], a0, b0); fma2(acc[0][1], a0, b1);
                fma2(acc[1][0], a1, b0); fma2(acc[1][1], a1, b1);
                fma2(acc[2][0], a2, b0); fma2(acc[2][1], a2, b1);
                fma2(acc[3][0], a3, b0); fma2(acc[3][1], a3, b1);
            }
            int oc4 = oc * 4;
            #pragma unroll
            for (int i = 0; i < 4; i++) {
                int row = er + 16 * i;
                int s = sSrc[row];
                float4 p = *(const float4*)(g_P + (size_t)s * 32 + oc4);
                float o0, o1, o2, o3;
                upk(acc[i][0], o0, o1);
                upk(acc[i][1], o2, o3);
                float v0 = fmaxf(o0 + p.x, 0.f);
                float v1 = fmaxf(o1 + p.y, 0.f);
                float v2 = fmaxf(o2 + p.z, 0.f);
                float v3 = fmaxf(o3 + p.w, 0.f);
                *(float4*)(e_out + (size_t)(e0 + row) * 32 + oc4) = make_float4(v0, v1, v2, v3);
                int b = row * 34 + oc4;
                sE[b] = v0; sE[b + 1] = v1; sE[b + 2] = v2; sE[b + 3] = v3;
            }
        }
        __syncthreads();

        // GEMM2: M1 = e @ W_e (registers), fused logits with warp-shuffle head reduce
        {
            u64t acc2[4][6];
            #pragma unroll
            for (int i = 0; i < 4; i++)
                #pragma unroll
                for (int j = 0; j < 6; j++) acc2[i][j] = 0ull;
            #pragma unroll 8
            for (int k = 0; k < 32; k++) {
                u64t a0 = pk(sE[rb0 + k]), a1 = pk(sE[rb1 + k]);
                u64t a2 = pk(sE[rb2 + k]), a3 = pk(sE[rb3 + k]);
                const u64t* bp = (const u64t*)(sW2 + k * 96 + c0);
                u64t b0 = bp[0], b1 = bp[1], b2 = bp[2], b3 = bp[3], b4 = bp[4], b5 = bp[5];
                fma2(acc2[0][0], a0, b0); fma2(acc2[0][1], a0, b1); fma2(acc2[0][2], a0, b2);
                fma2(acc2[0][3], a0, b3); fma2(acc2[0][4], a0, b4); fma2(acc2[0][5], a0, b5);
                fma2(acc2[1][0], a1, b0); fma2(acc2[1][1], a1, b1); fma2(acc2[1][2], a1, b2);
                fma2(acc2[1][3], a1, b3); fma2(acc2[1][4], a1, b4); fma2(acc2[1][5], a1, b5);
                fma2(acc2[2][0], a2, b0); fma2(acc2[2][1], a2, b1); fma2(acc2[2][2], a2, b2);
                fma2(acc2[2][3], a2, b3); fma2(acc2[2][4], a2, b4); fma2(acc2[2][5], a2, b5);
                fma2(acc2[3][0], a3, b0); fma2(acc2[3][1], a3, b1); fma2(acc2[3][2], a3, b2);
                fma2(acc2[3][3], a3, b3); fma2(acc2[3][4], a3, b4); fma2(acc2[3][5], a3, b5);
            }
            #pragma unroll
            for (int i = 0; i < 4; i++) {
                int row = er + 16 * i;
                int s = sSrc[row], d = sDst[row];
                const float4* xlp = (const float4*)(g_xl + (size_t)s * 96 + c0);
                const float4* xrp = (const float4*)(g_xr + (size_t)d * 96 + c0);
                float m1v[12];
                #pragma unroll
                for (int j = 0; j < 6; j++) upk(acc2[i][j], m1v[2 * j], m1v[2 * j + 1]);
                float pA = 0.f, pB = 0.f;
                #pragma unroll
                for (int q = 0; q < 3; q++) {
                    float4 xa = xlp[q], xb = xrp[q];
                    float mm[4];
                    mm[0] = m1v[q * 4 + 0] + xa.x + xb.x;
                    mm[1] = m1v[q * 4 + 1] + xa.y + xb.y;
                    mm[2] = m1v[q * 4 + 2] + xa.z + xb.z;
                    mm[3] = m1v[q * 4 + 3] + xa.w + xb.w;
                    #pragma unroll
                    for (int jj = 0; jj < 4; jj++) {
                        int j = q * 4 + jj;
                        float m = mm[jj];
                        m = (m > 0.f) ? m : 0.2f * m;
                        float v = m * attv[j];
                        if (j < split) pA += v; else pB += v;
                    }
                }
                // shuffle-reduce over the 8 column-group lanes into 3 head sums
                #pragma unroll
                for (int h = 0; h < 3; h++) {
                    float v = (hA == h ? pA : 0.f) + ((hB == h && hB != hA) ? pB : 0.f);
                    v += __shfl_xor_sync(0xffffffffu, v, 1);
                    v += __shfl_xor_sync(0xffffffffu, v, 2);
                    v += __shfl_xor_sync(0xffffffffu, v, 4);
                    if (oc == h) {
                        g_logits[(size_t)(e0 + row) * 3 + h] = v;
                        atomicMax(&g_mx[d * 3 + h], encf(v));
                    }
                }
            }
        }
        __syncthreads();
    }
}

// ======================= Kernel C: exp + denominator =======================
__global__ void __launch_bounds__(256) pass2K(const int* __restrict__ dstp)
{
    int e = blockIdx.x * 256 + threadIdx.x;
    if (e >= EE) return;
    int d = dstp[e];
    #pragma unroll
    for (int h = 0; h < 3; h++) {
        float lg = g_logits[(size_t)e * 3 + h];
        float mx = decf(g_mx[d * 3 + h]);
        float ex = __expf(lg - mx);
        g_logits[(size_t)e * 3 + h] = ex;
        atomicAdd(&g_den[d * 3 + h], ex);
    }
}

// ======================= Kernel C2: alpha = ex / den =======================
__global__ void __launch_bounds__(256) alphaK(const int* __restrict__ dstp)
{
    int e = blockIdx.x * 256 + threadIdx.x;
    if (e >= EE) return;
    int d = dstp[e];
    #pragma unroll
    for (int h = 0; h < 3; h++)
        g_logits[(size_t)e * 3 + h] /= g_den[d * 3 + h];
}

// ======================= Kernel D: message scatter (8 edges/warp, 6 red.v4/lane) ====
__global__ void __launch_bounds__(256) scatterK(const int* __restrict__ srcp,
                                                const int* __restrict__ dstp)
{
    int warp = blockIdx.x * 8 + (threadIdx.x >> 5);
    int lane = threadIdx.x & 31;
    int e0 = warp * 8;

    int s_own = 0, d_own = 0;
    if (lane < 8) { s_own = srcp[e0 + lane]; d_own = dstp[e0 + lane]; }
    float a_own = 0.f;
    if (lane < 24) {
        int es = lane / 3, h = lane - es * 3;
        a_own = g_logits[(size_t)(e0 + es) * 3 + h];   // holds alpha now
    }

    #pragma unroll
    for (int i = 0; i < 6; i++) {
        int idx = lane + 32 * i;        // 0..191
        int es = idx / 24;              // 0..7
        int chunk = idx - es * 24;      // 0..23
        int h = chunk >> 3;
        int s = __shfl_sync(0xffffffffu, s_own, es);
        int d = __shfl_sync(0xffffffffu, d_own, es);
        float al = __shfl_sync(0xffffffffu, a_own, es * 3 + h);
        float4 xv = *(const float4*)(g_xl + (size_t)s * 96 + chunk * 4);
        float* gp = g_gat + (size_t)d * 96 + chunk * 4;
        asm volatile("red.global.add.v4.f32 [%0], {%1,%2,%3,%4};"
                     :: "l"(gp), "f"(al * xv.x), "f"(al * xv.y),
                        "f"(al * xv.z), "f"(al * xv.w)
                     : "memory");
    }
}

// ======================= Kernel E: node_mlp_2 + batch sums =======================
__global__ void __launch_bounds__(128) node2K(
    const float* __restrict__ glob, const int* __restrict__ batch,
    const float* __restrict__ Wn2, const float* __restrict__ bn2,
    const float* __restrict__ bias_gat, float* __restrict__ xnew)
{
    extern __shared__ float sm[];
    float* sW  = sm;               // 128*32
    float* sR  = sW + 4096;        // 64*130
    float* sBg = sR + 64 * 130;    // 96
    float* sBn = sBg + 96;         // 32
    int* sBat  = (int*)(sBn + 32); // 64

    int t = threadIdx.x;
    for (int i = t; i < 4096; i += 128) sW[i] = Wn2[i];
    for (int i = t; i < 96; i += 128)   sBg[i] = bias_gat[i];
    if (t < 32) sBn[t] = bn2[t];

    int n0 = blockIdx.x * 64;
    if (t < 64) {
        int n = n0 + t;
        int bb = 0;
        if (n < NN) {
            bb = batch[n];
            atomicAdd(&g_bcnt[bb], 1);
        }
        sBat[t] = bb;
    }
    __syncthreads();

    for (int i = t; i < 64 * 128; i += 128) {
        int r = i >> 7, c = i & 127;
        int n = n0 + r;
        float v = 0.f;
        if (n < NN) {
            if (c < 96) v = g_gat[(size_t)n * 96 + c] + sBg[c];
            else        v = glob[sBat[r] * 32 + (c - 96)];
        }
        sR[r * 130 + c] = v;
    }
    __syncthreads();

    int er = t & 15, oc = t >> 4;
    int rb0 = er * 130, rb1 = rb0 + 16 * 130, rb2 = rb1 + 16 * 130, rb3 = rb2 + 16 * 130;

    u64t acc[4][2];
    #pragma unroll
    for (int i = 0; i < 4; i++) { acc[i][0] = 0ull; acc[i][1] = 0ull; }
    #pragma unroll 4
    for (int k = 0; k < 128; k++) {
        u64t a0 = pk(sR[rb0 + k]), a1 = pk(sR[rb1 + k]);
        u64t a2 = pk(sR[rb2 + k]), a3 = pk(sR[rb3 + k]);
        const u64t* bp = (const u64t*)(sW + k * 32 + oc * 4);
        u64t b0 = bp[0], b1 = bp[1];
        fma2(acc[0][0], a0, b0); fma2(acc[0][1], a0, b1);
        fma2(acc[1][0], a1, b0); fma2(acc[1][1], a1, b1);
        fma2(acc[2][0], a2, b0); fma2(acc[2][1], a2, b1);
        fma2(acc[3][0], a3, b0); fma2(acc[3][1], a3, b1);
    }

    #pragma unroll
    for (int i = 0; i < 4; i++) {
        int n = n0 + er + 16 * i;
        if (n < NN) {
            int bb = sBat[er + 16 * i];
            float o0, o1, o2, o3;
            upk(acc[i][0], o0, o1);
            upk(acc[i][1], o2, o3);
            float v0 = fmaxf(o0 + sBn[oc * 4 + 0], 0.f);
            float v1 = fmaxf(o1 + sBn[oc * 4 + 1], 0.f);
            float v2 = fmaxf(o2 + sBn[oc * 4 + 2], 0.f);
            float v3 = fmaxf(o3 + sBn[oc * 4 + 3], 0.f);
            *(float4*)(xnew + (size_t)n * 32 + oc * 4) = make_float4(v0, v1, v2, v3);
            atomicAdd(&g_bsum[bb * 32 + oc * 4 + 0], v0);
            atomicAdd(&g_bsum[bb * 32 + oc * 4 + 1], v1);
            atomicAdd(&g_bsum[bb * 32 + oc * 4 + 2], v2);
            atomicAdd(&g_bsum[bb * 32 + oc * 4 + 3], v3);
        }
    }
}

// ======================= Kernel F: global MLP =======================
__global__ void __launch_bounds__(256) globalK(
    const float* __restrict__ glob, const float* __restrict__ Wg,
    const float* __restrict__ bg, float* __restrict__ u_out)
{
    int p = blockIdx.x * 256 + threadIdx.x;
    if (p >= BBATCH * 32) return;
    int b = p >> 5, c = p & 31;
    float acc = bg[c];
    #pragma unroll
    for (int k = 0; k < 32; k++) acc += glob[b * 32 + k] * Wg[k * 32 + c];
    float cnt = fmaxf((float)g_bcnt[b], 1.f);
    float inv = 1.f / cnt;
    #pragma unroll
    for (int k = 0; k < 32; k++) acc += (g_bsum[b * 32 + k] * inv) * Wg[(32 + k) * 32 + c];
    u_out[p] = fmaxf(acc, 0.f);
}

// ======================= launch =======================
extern "C" void kernel_launch(void* const* d_in, const int* in_sizes, int n_in,
                              void* d_out, int out_size)
{
    const float* x        = (const float*)d_in[0];
    const float* ea       = (const float*)d_in[1];
    const float* glob     = (const float*)d_in[2];
    const float* W_edge   = (const float*)d_in[3];
    const float* b_edge   = (const float*)d_in[4];
    const float* W_l      = (const float*)d_in[5];
    const float* b_l      = (const float*)d_in[6];
    const float* W_r      = (const float*)d_in[7];
    const float* b_r      = (const float*)d_in[8];
    const float* W_e      = (const float*)d_in[9];
    const float* att      = (const float*)d_in[10];
    const float* bias_gat = (const float*)d_in[11];
    const float* W_n2     = (const float*)d_in[12];
    const float* b_n2     = (const float*)d_in[13];
    const float* W_g      = (const float*)d_in[14];
    const float* b_g      = (const float*)d_in[15];
    const int* eidx       = (const int*)d_in[16];
    const int* batch      = (const int*)d_in[17];
    const int* srcp = eidx;
    const int* dstp = eidx + EE;

    float* out  = (float*)d_out;
    float* o_x  = out;                       // [N,32]
    float* o_e  = out + (size_t)NN * 32;     // [E,32]
    float* o_u  = o_e + (size_t)EE * 32;     // [B,32]

    const int SMEM_A = (6144 + 6144 + 2048 + 64 * 66 + 96 + 96 + 32) * 4;   // ~75136
    const int SMEM_B = (1024 + 3072 + 64 * 34 + 64 * 34 + 128) * 4;         // ~34304
    const int SMEM_E = (4096 + 64 * 130 + 96 + 32) * 4 + 64 * 4;            // ~50432

    cudaFuncSetAttribute(nodeTransformK, cudaFuncAttributeMaxDynamicSharedMemorySize, SMEM_A);
    cudaFuncSetAttribute(edgeK,          cudaFuncAttributeMaxDynamicSharedMemorySize, SMEM_B);
    cudaFuncSetAttribute(node2K,         cudaFuncAttributeMaxDynamicSharedMemorySize, SMEM_E);

    void* p;
    cudaGetSymbolAddress(&p, g_mx);   cudaMemsetAsync(p, 0, (size_t)NN * 3 * 4);
    cudaGetSymbolAddress(&p, g_den);  cudaMemsetAsync(p, 0, (size_t)NN * 3 * 4);
    cudaGetSymbolAddress(&p, g_gat);  cudaMemsetAsync(p, 0, (size_t)NN * 96 * 4);
    cudaGetSymbolAddress(&p, g_bsum); cudaMemsetAsync(p, 0, (size_t)BBATCH * 32 * 4);
    cudaGetSymbolAddress(&p, g_bcnt); cudaMemsetAsync(p, 0, (size_t)BBATCH * 4);

    nodeTransformK<<<(NN + 63) / 64, 128, SMEM_A>>>(x, W_l, b_l, W_r, b_r, W_edge, b_edge);
    edgeK<<<888, 128, SMEM_B>>>(ea, W_edge, W_e, att, srcp, dstp, o_e);
    pass2K<<<(EE + 255) / 256, 256>>>(dstp);
    alphaK<<<(EE + 255) / 256, 256>>>(dstp);
    scatterK<<<EE / 64, 256>>>(srcp, dstp);
    node2K<<<(NN + 63) / 64, 128, SMEM_E>>>(glob, batch, W_n2, b_n2, bias_gat, o_x);
    globalK<<<(BBATCH * 32 + 255) / 256, 256>>>(glob, W_g, b_g, o_u);
}